// round 3
// baseline (speedup 1.0000x reference)
#include <cuda_runtime.h>

// Problem constants (match reference)
#define BOX   120
#define VOL   (BOX * BOX * BOX)       // 1,728,000
#define NTYPE 11
#define BATCH 4
#define BT    (BATCH * NTYPE)         // 44
#define MAXA  512
#define NNB   2
#define NCOLS (BT * BOX * BOX)        // 633,600 (bt, x, y) columns
#define CAP   16                      // max atoms per dilated column

// Static device scratch (allocation-free per harness rules).
__device__ int    g_cnt[NCOLS];            // per-column atom count (2.5 MB)
__device__ float4 g_entry[(long long)NCOLS * CAP];  // per-column atom payloads (~162 MB)

// ---------------------------------------------------------------------------
// num_atoms dtype sniff: values in [1,512]. If int64 (LE), 32-bit word 1 is
// the zero high half of element 0; if int32, word 1 is num_atoms[1] >= 1.
// ---------------------------------------------------------------------------
__device__ __forceinline__ int get_natoms(const int* __restrict__ p, int bt) {
    return (p[1] == 0) ? p[2 * bt] : p[bt];
}

// ---------------------------------------------------------------------------
// Kernel 1: zero the column counters (2.5 MB).
// ---------------------------------------------------------------------------
__global__ void __launch_bounds__(256) zero_cnt_kernel() {
    int i = blockIdx.x * blockDim.x + threadIdx.x;
    if (i < NCOLS) g_cnt[i] = 0;
}

// ---------------------------------------------------------------------------
// Kernel 2: dilated binning. One thread per (bt, atom); pushes the atom's
// payload into every (x +- 2, y +- 2) column whose voxels it can touch.
// ---------------------------------------------------------------------------
__global__ void __launch_bounds__(256) bin_kernel(
    const float* __restrict__ coords,    // [BT, 3*MAXA]
    const int* __restrict__ num_atoms)
{
    int t = blockIdx.x * blockDim.x + threadIdx.x;
    if (t >= BT * MAXA) return;
    const int bt = t >> 9;           // / MAXA
    const int a  = t & (MAXA - 1);
    if (a >= get_natoms(num_atoms, bt)) return;

    const float* p = coords + (long long)bt * (3 * MAXA) + 3 * a;
    const float x = p[0], y = p[1], z = p[2];
    const int cx = (int)floorf(x);
    const int cy = (int)floorf(y);
    const float4 payload = make_float4(x, y, z, 0.f);

    #pragma unroll
    for (int dx = -NNB; dx <= NNB; dx++) {
        const int ix = cx + dx;
        if ((unsigned)ix >= BOX) continue;
        #pragma unroll
        for (int dy = -NNB; dy <= NNB; dy++) {
            const int iy = cy + dy;
            if ((unsigned)iy >= BOX) continue;
            const int col = (bt * BOX + ix) * BOX + iy;
            const int slot = atomicAdd(&g_cnt[col], 1);
            if (slot < CAP)
                g_entry[(long long)col * CAP + slot] = payload;
        }
    }
}

// ---------------------------------------------------------------------------
// Kernel 3: gather + streaming write. One warp per (bt,x,y) row of 120
// z-voxels; lane l writes z in [4l, 4l+3] as a float4 (rows are 16B-aligned:
// 480 B each). Most rows have zero atoms -> pure streaming zero-write.
// ---------------------------------------------------------------------------
__global__ void __launch_bounds__(128) gather_kernel(float* __restrict__ out) {
    const int row = blockIdx.x * 4 + (threadIdx.x >> 5);   // < NCOLS exactly
    const int lane = threadIdx.x & 31;

    int n = g_cnt[row];
    n = n < CAP ? n : CAP;

    float a0 = 0.f, a1 = 0.f, a2 = 0.f, a3 = 0.f;

    if (n > 0) {
        const int r  = row % (BOX * BOX);
        const float fx = (float)(r / BOX);
        const float fy = (float)(r % BOX);
        const int zb = lane * 4;
        const float4* ent = &g_entry[(long long)row * CAP];
        for (int i = 0; i < n; i++) {
            const float4 at = ent[i];          // same-address -> L1 broadcast
            const float dx = fx - at.x;
            const float dy = fy - at.y;
            const float rxy = dx * dx + dy * dy;
            const int cz = (int)floorf(at.z);
            #pragma unroll
            for (int j = 0; j < 4; j++) {
                const int z = zb + j;
                if ((unsigned)(z - cz + NNB) <= 2u * NNB) {
                    const float dz = (float)z - at.z;
                    const float v = __expf(-(rxy + dz * dz));
                    if (j == 0) a0 += v;
                    else if (j == 1) a1 += v;
                    else if (j == 2) a2 += v;
                    else a3 += v;
                }
            }
        }
    }

    if (lane < BOX / 4) {
        float4* outp = (float4*)(out + (long long)row * BOX);
        outp[lane] = make_float4(a0, a1, a2, a3);
    }
}

// ---------------------------------------------------------------------------
extern "C" void kernel_launch(void* const* d_in, const int* in_sizes, int n_in,
                              void* d_out, int out_size) {
    const float* coords    = (const float*)d_in[0];  // float32 [4,11,1536]
    const int*   num_atoms = (const int*)d_in[1];    // int32/int64 [4,11]
    float*       out       = (float*)d_out;          // float32 [4,11,120,120,120]

    zero_cnt_kernel<<<(NCOLS + 255) / 256, 256>>>();
    bin_kernel<<<(BT * MAXA + 255) / 256, 256>>>(coords, num_atoms);
    gather_kernel<<<NCOLS / 4, 128>>>(out);
}

// round 4
// speedup vs baseline: 2.0553x; 2.0553x over previous
#include <cuda_runtime.h>

// Problem constants (match reference)
#define BOX   120
#define VOL   (BOX * BOX * BOX)       // 1,728,000
#define NTYPE 11
#define BATCH 4
#define BT    (BATCH * NTYPE)         // 44
#define MAXA  512
#define NNB   2
#define KTOT  125                     // (2*NNB+1)^3

#define NCHUNK     4
#define BT_CHUNK   (BT / NCHUNK)                      // 11
#define FLOATS_PER_CHUNK ((long long)BT_CHUNK * VOL)  // 19,008,000
#define F4_PER_CHUNK     (FLOATS_PER_CHUNK / 4)       // 4,752,000

// ---------------------------------------------------------------------------
// num_atoms dtype sniff: values in [1,512]. If int64 (LE), 32-bit word 1 is
// the zero high half of element 0; if int32, word 1 is num_atoms[1] >= 1.
// ---------------------------------------------------------------------------
__device__ __forceinline__ int get_natoms(const int* __restrict__ p, int bt) {
    return (p[1] == 0) ? p[2 * bt] : p[bt];
}

// ---------------------------------------------------------------------------
// Zero one chunk of the output (write-only, float4, at HBM write ceiling).
// ---------------------------------------------------------------------------
__global__ void __launch_bounds__(256) zero_kernel(float4* __restrict__ out, long long n4) {
    long long i = (long long)blockIdx.x * blockDim.x + threadIdx.x;
    if (i < n4) out[i] = make_float4(0.f, 0.f, 0.f, 0.f);
}

// ---------------------------------------------------------------------------
// Warp-per-atom scatter for one bt-chunk. 256 threads = 8 warps = 8 atoms per
// block; each lane handles up to 4 of the 125 neighbor cells. atomicAdd result
// unused -> REDG.
// ---------------------------------------------------------------------------
__global__ void __launch_bounds__(256) scatter_kernel(
    const float* __restrict__ coords,    // [BT, 3*MAXA]
    const int* __restrict__ num_atoms,   // [BT] int32 (or int64, sniffed)
    float* __restrict__ out,             // [BT, VOL]
    int bt0)                             // first bt of this chunk
{
    const int w    = blockIdx.x * 8 + (threadIdx.x >> 5);  // warp id within chunk
    const int lane = threadIdx.x & 31;
    const int bt   = bt0 + (w >> 9);       // w / MAXA
    const int a    = w & (MAXA - 1);
    if (a >= get_natoms(num_atoms, bt)) return;

    const float* p = coords + (long long)bt * (3 * MAXA) + 3 * a;
    const float x = p[0];                 // same-address within warp -> broadcast
    const float y = p[1];
    const float z = p[2];
    const int cx = (int)floorf(x);
    const int cy = (int)floorf(y);
    const int cz = (int)floorf(z);

    float* vol = out + (long long)bt * VOL;

    #pragma unroll
    for (int t = 0; t < 4; t++) {
        const int k = lane + t * 32;
        if (k < KTOT) {
            const int ix = cx + k / 25 - NNB;
            const int iy = cy + (k / 5) % 5 - NNB;
            const int iz = cz + k % 5 - NNB;
            if ((unsigned)ix < BOX && (unsigned)iy < BOX && (unsigned)iz < BOX) {
                const float dx = (float)ix - x;
                const float dy = (float)iy - y;
                const float dz = (float)iz - z;
                const float v = __expf(-(dx * dx + dy * dy + dz * dz));
                atomicAdd(vol + ((long long)ix * BOX + iy) * BOX + iz, v);
            }
        }
    }
}

// ---------------------------------------------------------------------------
// Stream/event setup at static-init time (host-side objects; created before
// the harness's device-memory checkpoints; never destroyed).
// ---------------------------------------------------------------------------
static cudaStream_t g_s1 = nullptr;
static cudaEvent_t  g_evZ[NCHUNK];
static cudaEvent_t  g_evJoin = nullptr;
static bool         g_forked = false;

namespace {
struct StreamInit {
    StreamInit() {
        bool ok = (cudaStreamCreateWithFlags(&g_s1, cudaStreamNonBlocking) == cudaSuccess);
        for (int i = 0; i < NCHUNK && ok; i++)
            ok = (cudaEventCreateWithFlags(&g_evZ[i], cudaEventDisableTiming) == cudaSuccess);
        if (ok)
            ok = (cudaEventCreateWithFlags(&g_evJoin, cudaEventDisableTiming) == cudaSuccess);
        g_forked = ok;
    }
};
static StreamInit g_stream_init;
}  // namespace

// ---------------------------------------------------------------------------
extern "C" void kernel_launch(void* const* d_in, const int* in_sizes, int n_in,
                              void* d_out, int out_size) {
    const float* coords    = (const float*)d_in[0];  // float32 [4,11,1536]
    const int*   num_atoms = (const int*)d_in[1];    // int32/int64 [4,11]
    float*       out       = (float*)d_out;          // float32 [4,11,120,120,120]

    const int zblocks = (int)((F4_PER_CHUNK + 255) / 256);
    const int sblocks = (BT_CHUNK * MAXA) / 8;       // 704 blocks per chunk

    if (g_forked) {
        // Pipelined: zeros run back-to-back on the main stream; each chunk's
        // scatter runs on the forked stream once its zero completes.
        for (int c = 0; c < NCHUNK; c++) {
            float4* chunk = (float4*)d_out + (long long)c * F4_PER_CHUNK;
            zero_kernel<<<zblocks, 256>>>(chunk, F4_PER_CHUNK);
            cudaEventRecord(g_evZ[c], 0);
            cudaStreamWaitEvent(g_s1, g_evZ[c], 0);
            scatter_kernel<<<sblocks, 256, 0, g_s1>>>(coords, num_atoms, out, c * BT_CHUNK);
        }
        cudaEventRecord(g_evJoin, g_s1);
        cudaStreamWaitEvent(0, g_evJoin, 0);
    } else {
        // Fallback: sequential on the default stream (still correct).
        for (int c = 0; c < NCHUNK; c++) {
            float4* chunk = (float4*)d_out + (long long)c * F4_PER_CHUNK;
            zero_kernel<<<zblocks, 256>>>(chunk, F4_PER_CHUNK);
        }
        for (int c = 0; c < NCHUNK; c++) {
            scatter_kernel<<<sblocks, 256>>>(coords, num_atoms, out, c * BT_CHUNK);
        }
    }
}